// round 5
// baseline (speedup 1.0000x reference)
#include <cuda_runtime.h>

#define NN   100000
#define NE   1000000
#define NG   2048
#define HID  64
#define ODIM 128

__device__ float d_dinv[NN];
__device__ int   d_cnt_in[NN];     // in-degree (edges only)
__device__ int   d_row[NN];        // CSR row offsets (exclusive prefix of cnt_in)
__device__ int   d_fill[NN];       // slot counters for CSR build
__device__ int   d_csrc[NE];       // CSR: src node per slot
__device__ float d_cw[NE];         // CSR: edge norm per slot
__device__ float d_h[NN * HID];    // x @ W1
__device__ float d_g[NN * HID];    // relu(h1) @ W2
__device__ float d_pool[NG * HID]; // per-graph sums
__device__ float d_cnt[NG];        // per-graph node counts

__device__ __forceinline__ void red_v4(float* ap, float a, float b, float c, float d) {
    asm volatile("red.global.add.v4.f32 [%0], {%1, %2, %3, %4};"
                 :: "l"(ap), "f"(a), "f"(b), "f"(c), "f"(d) : "memory");
}

__global__ void k_zero() {
    int i = blockIdx.x * blockDim.x + threadIdx.x;
    if (i < NN) { d_cnt_in[i] = 0; d_fill[i] = 0; }
    if (i < NG * HID / 4)
        reinterpret_cast<float4*>(d_pool)[i] = make_float4(0.f, 0.f, 0.f, 0.f);
    if (i < NG) d_cnt[i] = 0.f;
}

__global__ void k_hist(const int* __restrict__ dst) {
    int i = blockIdx.x * blockDim.x + threadIdx.x;
    if (i < NE) atomicAdd(&d_cnt_in[dst[i]], 1);
}

__global__ void k_dinv() {
    int i = blockIdx.x * blockDim.x + threadIdx.x;
    if (i < NN) d_dinv[i] = rsqrtf((float)(d_cnt_in[i] + 1));  // +1 self-loop
}

// single-block exclusive scan of d_cnt_in -> d_row  (1024 threads, ~98 elems each)
__global__ void __launch_bounds__(1024) k_scan() {
    __shared__ int ssum[1024];
    const int PER = (NN + 1023) / 1024;
    int tid = threadIdx.x;
    int base = tid * PER;
    int s = 0;
    #pragma unroll 1
    for (int i = 0; i < PER; i++) {
        int idx = base + i;
        if (idx < NN) s += d_cnt_in[idx];
    }
    ssum[tid] = s;
    __syncthreads();
    // Hillis-Steele inclusive scan over 1024 partials
    for (int off = 1; off < 1024; off <<= 1) {
        int t = (tid >= off) ? ssum[tid - off] : 0;
        __syncthreads();
        ssum[tid] += t;
        __syncthreads();
    }
    int run = ssum[tid] - s;  // exclusive offset for this thread's chunk
    #pragma unroll 1
    for (int i = 0; i < PER; i++) {
        int idx = base + i;
        if (idx < NN) { d_row[idx] = run; run += d_cnt_in[idx]; }
    }
}

// place each edge into its dst's CSR range; store (src, norm)
__global__ void k_build(const int* __restrict__ src, const int* __restrict__ dst) {
    int e = blockIdx.x * blockDim.x + threadIdx.x;
    if (e >= NE) return;
    int s = src[e], d = dst[e];
    int slot = d_row[d] + atomicAdd(&d_fill[d], 1);
    d_csrc[slot] = s;
    d_cw[slot] = d_dinv[s] * d_dinv[d];
}

// h = x @ W1   (x: [NN,5], W1: [5,64]); 16 lanes/node, float4 stores
__global__ void k_xw1(const float* __restrict__ x, const float* __restrict__ W1) {
    __shared__ float W1s[5 * HID];
    int tid = threadIdx.x;
    for (int i = tid; i < 5 * HID; i += blockDim.x) W1s[i] = W1[i];
    __syncthreads();
    int t = blockIdx.x * blockDim.x + tid;
    int n = t >> 4, c = t & 15;
    if (n >= NN) return;
    float xv[5];
#pragma unroll
    for (int k = 0; k < 5; k++) xv[k] = x[n * 5 + k];
    float o[4];
#pragma unroll
    for (int j = 0; j < 4; j++) {
        float s = 0.f;
#pragma unroll
        for (int k = 0; k < 5; k++) s += xv[k] * W1s[k * HID + c * 4 + j];
        o[j] = s;
    }
    *reinterpret_cast<float4*>(&d_h[(size_t)n * HID + c * 4]) =
        make_float4(o[0], o[1], o[2], o[3]);
}

// layer 1 fused: agg = CSR-gather(h) + self-loop; h1 = relu(agg + b1); g = h1 @ W2
// 16 nodes/block, 16 lanes/node
__global__ void __launch_bounds__(256) k_layer1(const float* __restrict__ b1,
                                                const float* __restrict__ W2) {
    __shared__ float W2s[HID * HID];
    __shared__ float h1s[16 * HID];
    __shared__ float b1s[HID];
    int tid = threadIdx.x;
    for (int i = tid; i < HID * HID; i += 256) W2s[i] = W2[i];
    if (tid < HID) b1s[tid] = b1[tid];
    __syncthreads();

    int nl = tid >> 4, c = tid & 15;
    int node = blockIdx.x * 16 + nl;
    if (node < NN) {
        int start = d_row[node], deg = d_cnt_in[node];
        float acc0 = 0.f, acc1 = 0.f, acc2 = 0.f, acc3 = 0.f;
        for (int j = 0; j < deg; j++) {
            int s = __ldg(&d_csrc[start + j]);
            float w = __ldg(&d_cw[start + j]);
            float4 v = *reinterpret_cast<const float4*>(&d_h[(size_t)s * HID + c * 4]);
            acc0 += v.x * w; acc1 += v.y * w; acc2 += v.z * w; acc3 += v.w * w;
        }
        float di = d_dinv[node];
        float sl = di * di;
        float4 hv = *reinterpret_cast<const float4*>(&d_h[(size_t)node * HID + c * 4]);
        h1s[nl * HID + c * 4 + 0] = fmaxf(acc0 + hv.x * sl + b1s[c * 4 + 0], 0.f);
        h1s[nl * HID + c * 4 + 1] = fmaxf(acc1 + hv.y * sl + b1s[c * 4 + 1], 0.f);
        h1s[nl * HID + c * 4 + 2] = fmaxf(acc2 + hv.z * sl + b1s[c * 4 + 2], 0.f);
        h1s[nl * HID + c * 4 + 3] = fmaxf(acc3 + hv.w * sl + b1s[c * 4 + 3], 0.f);
    } else {
#pragma unroll
        for (int j = 0; j < 4; j++) h1s[nl * HID + c * 4 + j] = 0.f;
    }
    __syncthreads();

    if (node < NN) {
        float o0 = 0.f, o1 = 0.f, o2 = 0.f, o3 = 0.f;
#pragma unroll
        for (int k = 0; k < HID; k++) {
            float hv = h1s[nl * HID + k];
            o0 += hv * W2s[k * HID + c * 4 + 0];
            o1 += hv * W2s[k * HID + c * 4 + 1];
            o2 += hv * W2s[k * HID + c * 4 + 2];
            o3 += hv * W2s[k * HID + c * 4 + 3];
        }
        *reinterpret_cast<float4*>(&d_g[(size_t)node * HID + c * 4]) =
            make_float4(o0, o1, o2, o3);
    }
}

// layer 2 fused: agg = CSR-gather(g) + self-loop; h2 = relu(agg + b2);
// pool[batch[n]] += h2 (red.v4); cnt[batch[n]] += 1
__global__ void __launch_bounds__(256) k_layer2(const float* __restrict__ b2,
                                                const int* __restrict__ batch) {
    int t = blockIdx.x * blockDim.x + threadIdx.x;
    int n = t >> 4, c = t & 15;
    if (n >= NN) return;
    int start = d_row[n], deg = d_cnt_in[n];
    float acc0 = 0.f, acc1 = 0.f, acc2 = 0.f, acc3 = 0.f;
    for (int j = 0; j < deg; j++) {
        int s = __ldg(&d_csrc[start + j]);
        float w = __ldg(&d_cw[start + j]);
        float4 v = *reinterpret_cast<const float4*>(&d_g[(size_t)s * HID + c * 4]);
        acc0 += v.x * w; acc1 += v.y * w; acc2 += v.z * w; acc3 += v.w * w;
    }
    float di = d_dinv[n];
    float sl = di * di;
    float4 gv = *reinterpret_cast<const float4*>(&d_g[(size_t)n * HID + c * 4]);
    float o0 = fmaxf(acc0 + gv.x * sl + b2[c * 4 + 0], 0.f);
    float o1 = fmaxf(acc1 + gv.y * sl + b2[c * 4 + 1], 0.f);
    float o2 = fmaxf(acc2 + gv.z * sl + b2[c * 4 + 2], 0.f);
    float o3 = fmaxf(acc3 + gv.w * sl + b2[c * 4 + 3], 0.f);
    int g = batch[n];
    red_v4(&d_pool[g * HID + c * 4], o0, o1, o2, o3);
    if (c == 0) atomicAdd(&d_cnt[g], 1.0f);
}

// per-graph: pooled = pool/max(cnt,1); z = relu(pooled@W3+b3); out = z@W4+b4
__global__ void k_head(const float* __restrict__ W3, const float* __restrict__ b3,
                       const float* __restrict__ W4, const float* __restrict__ b4,
                       float* __restrict__ out) {
    __shared__ float p[HID];
    __shared__ float z[HID];
    int g = blockIdx.x, tid = threadIdx.x;
    if (tid < HID) {
        float cnt = fmaxf(d_cnt[g], 1.0f);
        p[tid] = d_pool[g * HID + tid] / cnt;
    }
    __syncthreads();
    if (tid < HID) {
        float s = b3[tid];
#pragma unroll
        for (int k = 0; k < HID; k++) s += p[k] * W3[k * HID + tid];
        z[tid] = fmaxf(s, 0.f);
    }
    __syncthreads();
    float s = b4[tid];
#pragma unroll
    for (int k = 0; k < HID; k++) s += z[k] * W4[k * ODIM + tid];
    out[g * ODIM + tid] = s;
}

extern "C" void kernel_launch(void* const* d_in, const int* in_sizes, int n_in,
                              void* d_out, int out_size) {
    const float* x     = (const float*)d_in[0];
    const int*   ei    = (const int*)d_in[1];
    const int*   batch = (const int*)d_in[2];
    const float* W1 = (const float*)d_in[3];
    const float* b1 = (const float*)d_in[4];
    const float* W2 = (const float*)d_in[5];
    const float* b2 = (const float*)d_in[6];
    const float* W3 = (const float*)d_in[7];
    const float* b3 = (const float*)d_in[8];
    const float* W4 = (const float*)d_in[9];
    const float* b4 = (const float*)d_in[10];
    float* out = (float*)d_out;

    const int* src = ei;        // edge_index[0, :]
    const int* dst = ei + NE;   // edge_index[1, :]

    k_zero<<<(NN + 255) / 256, 256>>>();
    k_hist<<<(NE + 255) / 256, 256>>>(dst);
    k_dinv<<<(NN + 255) / 256, 256>>>();
    k_scan<<<1, 1024>>>();
    k_build<<<(NE + 255) / 256, 256>>>(src, dst);
    k_xw1<<<(NN * 16 + 255) / 256, 256>>>(x, W1);
    k_layer1<<<(NN + 15) / 16, 256>>>(b1, W2);
    k_layer2<<<(NN * 16 + 255) / 256, 256>>>(b2, batch);
    k_head<<<NG, 128>>>(W3, b3, W4, b4, out);
}

// round 6
// speedup vs baseline: 1.5439x; 1.5439x over previous
#include <cuda_runtime.h>

#define NN   100000
#define NE   1000000
#define NG   2048
#define HID  64
#define ODIM 128

#define SCAN_T   256
#define SCAN_C   4
#define SCAN_NPB (SCAN_T * SCAN_C)                  // 1024 nodes per block
#define SCAN_B   ((NN + SCAN_NPB - 1) / SCAN_NPB)   // 98 blocks

__device__ float d_dinv[NN];
__device__ int   d_cnt_in[NN];     // in-degree (edges only)
__device__ int   d_row[NN];        // CSR row offsets (exclusive prefix of cnt_in)
__device__ int   d_fill[NN];       // slot counters for CSR build
__device__ int   d_csrc[NE];       // CSR: src node per slot
__device__ float d_cw[NE];         // CSR: edge norm per slot
__device__ float d_h[NN * HID];    // x @ W1
__device__ float d_g[NN * HID];    // relu(h1) @ W2
__device__ float d_pool[NG * HID]; // per-graph sums
__device__ float d_cnt[NG];        // per-graph node counts
__device__ int   d_bsum[SCAN_B];   // per-block totals
__device__ int   d_boff[SCAN_B];   // per-block exclusive offsets
__device__ int   d_toff[SCAN_B * SCAN_T]; // per-thread exclusive offsets (within block)

__device__ __forceinline__ void red_v4(float* ap, float a, float b, float c, float d) {
    asm volatile("red.global.add.v4.f32 [%0], {%1, %2, %3, %4};"
                 :: "l"(ap), "f"(a), "f"(b), "f"(c), "f"(d) : "memory");
}

__global__ void k_zero() {
    int i = blockIdx.x * blockDim.x + threadIdx.x;
    if (i < NN) { d_cnt_in[i] = 0; d_fill[i] = 0; }
    if (i < NG * HID / 4)
        reinterpret_cast<float4*>(d_pool)[i] = make_float4(0.f, 0.f, 0.f, 0.f);
    if (i < NG) d_cnt[i] = 0.f;
}

__global__ void k_hist(const int* __restrict__ dst) {
    int i = blockIdx.x * blockDim.x + threadIdx.x;
    if (i < NE) atomicAdd(&d_cnt_in[dst[i]], 1);
}

__global__ void k_dinv() {
    int i = blockIdx.x * blockDim.x + threadIdx.x;
    if (i < NN) d_dinv[i] = rsqrtf((float)(d_cnt_in[i] + 1));  // +1 self-loop
}

// ---- 3-phase decoupled scan of d_cnt_in -> d_row ----
__global__ void __launch_bounds__(SCAN_T) k_scanA() {
    __shared__ int sh[SCAN_T];
    int b = blockIdx.x, tid = threadIdx.x;
    int base = b * SCAN_NPB + tid * SCAN_C;
    int s = 0;
#pragma unroll
    for (int i = 0; i < SCAN_C; i++) {
        int idx = base + i;
        if (idx < NN) s += d_cnt_in[idx];
    }
    sh[tid] = s;
    __syncthreads();
    for (int off = 1; off < SCAN_T; off <<= 1) {
        int t = (tid >= off) ? sh[tid - off] : 0;
        __syncthreads();
        sh[tid] += t;
        __syncthreads();
    }
    d_toff[b * SCAN_T + tid] = sh[tid] - s;       // exclusive within block
    if (tid == SCAN_T - 1) d_bsum[b] = sh[tid];   // block total
}

__global__ void __launch_bounds__(128) k_scanB() {
    __shared__ int sh[128];
    int tid = threadIdx.x;
    int s = (tid < SCAN_B) ? d_bsum[tid] : 0;
    sh[tid] = s;
    __syncthreads();
    for (int off = 1; off < 128; off <<= 1) {
        int t = (tid >= off) ? sh[tid - off] : 0;
        __syncthreads();
        sh[tid] += t;
        __syncthreads();
    }
    if (tid < SCAN_B) d_boff[tid] = sh[tid] - s;  // exclusive across blocks
}

__global__ void __launch_bounds__(SCAN_T) k_scanC() {
    int b = blockIdx.x, tid = threadIdx.x;
    int run = d_boff[b] + d_toff[b * SCAN_T + tid];
    int base = b * SCAN_NPB + tid * SCAN_C;
#pragma unroll
    for (int i = 0; i < SCAN_C; i++) {
        int idx = base + i;
        if (idx < NN) { d_row[idx] = run; run += d_cnt_in[idx]; }
    }
}

// place each edge into its dst's CSR range; store (src, norm)
__global__ void k_build(const int* __restrict__ src, const int* __restrict__ dst) {
    int e = blockIdx.x * blockDim.x + threadIdx.x;
    if (e >= NE) return;
    int s = src[e], d = dst[e];
    int slot = d_row[d] + atomicAdd(&d_fill[d], 1);
    d_csrc[slot] = s;
    d_cw[slot] = d_dinv[s] * d_dinv[d];
}

// h = x @ W1   (x: [NN,5], W1: [5,64]); 16 lanes/node, float4 stores
__global__ void k_xw1(const float* __restrict__ x, const float* __restrict__ W1) {
    __shared__ float W1s[5 * HID];
    int tid = threadIdx.x;
    for (int i = tid; i < 5 * HID; i += blockDim.x) W1s[i] = W1[i];
    __syncthreads();
    int t = blockIdx.x * blockDim.x + tid;
    int n = t >> 4, c = t & 15;
    if (n >= NN) return;
    float xv[5];
#pragma unroll
    for (int k = 0; k < 5; k++) xv[k] = x[n * 5 + k];
    float o[4];
#pragma unroll
    for (int j = 0; j < 4; j++) {
        float s = 0.f;
#pragma unroll
        for (int k = 0; k < 5; k++) s += xv[k] * W1s[k * HID + c * 4 + j];
        o[j] = s;
    }
    *reinterpret_cast<float4*>(&d_h[(size_t)n * HID + c * 4]) =
        make_float4(o[0], o[1], o[2], o[3]);
}

// layer 1 fused: agg = CSR-gather(h) + self-loop; h1 = relu(agg + b1); g = h1 @ W2
__global__ void __launch_bounds__(256) k_layer1(const float* __restrict__ b1,
                                                const float* __restrict__ W2) {
    __shared__ float W2s[HID * HID];
    __shared__ float h1s[16 * HID];
    __shared__ float b1s[HID];
    int tid = threadIdx.x;
    for (int i = tid; i < HID * HID; i += 256) W2s[i] = W2[i];
    if (tid < HID) b1s[tid] = b1[tid];
    __syncthreads();

    int nl = tid >> 4, c = tid & 15;
    int node = blockIdx.x * 16 + nl;
    if (node < NN) {
        int start = d_row[node], deg = d_cnt_in[node];
        float acc0 = 0.f, acc1 = 0.f, acc2 = 0.f, acc3 = 0.f;
        for (int j = 0; j < deg; j++) {
            int s = __ldg(&d_csrc[start + j]);
            float w = __ldg(&d_cw[start + j]);
            float4 v = *reinterpret_cast<const float4*>(&d_h[(size_t)s * HID + c * 4]);
            acc0 += v.x * w; acc1 += v.y * w; acc2 += v.z * w; acc3 += v.w * w;
        }
        float di = d_dinv[node];
        float sl = di * di;
        float4 hv = *reinterpret_cast<const float4*>(&d_h[(size_t)node * HID + c * 4]);
        h1s[nl * HID + c * 4 + 0] = fmaxf(acc0 + hv.x * sl + b1s[c * 4 + 0], 0.f);
        h1s[nl * HID + c * 4 + 1] = fmaxf(acc1 + hv.y * sl + b1s[c * 4 + 1], 0.f);
        h1s[nl * HID + c * 4 + 2] = fmaxf(acc2 + hv.z * sl + b1s[c * 4 + 2], 0.f);
        h1s[nl * HID + c * 4 + 3] = fmaxf(acc3 + hv.w * sl + b1s[c * 4 + 3], 0.f);
    } else {
#pragma unroll
        for (int j = 0; j < 4; j++) h1s[nl * HID + c * 4 + j] = 0.f;
    }
    __syncthreads();

    if (node < NN) {
        float o0 = 0.f, o1 = 0.f, o2 = 0.f, o3 = 0.f;
#pragma unroll
        for (int k = 0; k < HID; k++) {
            float hv = h1s[nl * HID + k];
            o0 += hv * W2s[k * HID + c * 4 + 0];
            o1 += hv * W2s[k * HID + c * 4 + 1];
            o2 += hv * W2s[k * HID + c * 4 + 2];
            o3 += hv * W2s[k * HID + c * 4 + 3];
        }
        *reinterpret_cast<float4*>(&d_g[(size_t)node * HID + c * 4]) =
            make_float4(o0, o1, o2, o3);
    }
}

// layer 2 fused: agg = CSR-gather(g) + self-loop; h2 = relu(agg + b2);
// pool[batch[n]] += h2 (red.v4); cnt[batch[n]] += 1
__global__ void __launch_bounds__(256) k_layer2(const float* __restrict__ b2,
                                                const int* __restrict__ batch) {
    int t = blockIdx.x * blockDim.x + threadIdx.x;
    int n = t >> 4, c = t & 15;
    if (n >= NN) return;
    int start = d_row[n], deg = d_cnt_in[n];
    float acc0 = 0.f, acc1 = 0.f, acc2 = 0.f, acc3 = 0.f;
    for (int j = 0; j < deg; j++) {
        int s = __ldg(&d_csrc[start + j]);
        float w = __ldg(&d_cw[start + j]);
        float4 v = *reinterpret_cast<const float4*>(&d_g[(size_t)s * HID + c * 4]);
        acc0 += v.x * w; acc1 += v.y * w; acc2 += v.z * w; acc3 += v.w * w;
    }
    float di = d_dinv[n];
    float sl = di * di;
    float4 gv = *reinterpret_cast<const float4*>(&d_g[(size_t)n * HID + c * 4]);
    float o0 = fmaxf(acc0 + gv.x * sl + b2[c * 4 + 0], 0.f);
    float o1 = fmaxf(acc1 + gv.y * sl + b2[c * 4 + 1], 0.f);
    float o2 = fmaxf(acc2 + gv.z * sl + b2[c * 4 + 2], 0.f);
    float o3 = fmaxf(acc3 + gv.w * sl + b2[c * 4 + 3], 0.f);
    int g = batch[n];
    red_v4(&d_pool[g * HID + c * 4], o0, o1, o2, o3);
    if (c == 0) atomicAdd(&d_cnt[g], 1.0f);
}

// per-graph: pooled = pool/max(cnt,1); z = relu(pooled@W3+b3); out = z@W4+b4
__global__ void k_head(const float* __restrict__ W3, const float* __restrict__ b3,
                       const float* __restrict__ W4, const float* __restrict__ b4,
                       float* __restrict__ out) {
    __shared__ float p[HID];
    __shared__ float z[HID];
    int g = blockIdx.x, tid = threadIdx.x;
    if (tid < HID) {
        float cnt = fmaxf(d_cnt[g], 1.0f);
        p[tid] = d_pool[g * HID + tid] / cnt;
    }
    __syncthreads();
    if (tid < HID) {
        float s = b3[tid];
#pragma unroll
        for (int k = 0; k < HID; k++) s += p[k] * W3[k * HID + tid];
        z[tid] = fmaxf(s, 0.f);
    }
    __syncthreads();
    float s = b4[tid];
#pragma unroll
    for (int k = 0; k < HID; k++) s += z[k] * W4[k * ODIM + tid];
    out[g * ODIM + tid] = s;
}

extern "C" void kernel_launch(void* const* d_in, const int* in_sizes, int n_in,
                              void* d_out, int out_size) {
    const float* x     = (const float*)d_in[0];
    const int*   ei    = (const int*)d_in[1];
    const int*   batch = (const int*)d_in[2];
    const float* W1 = (const float*)d_in[3];
    const float* b1 = (const float*)d_in[4];
    const float* W2 = (const float*)d_in[5];
    const float* b2 = (const float*)d_in[6];
    const float* W3 = (const float*)d_in[7];
    const float* b3 = (const float*)d_in[8];
    const float* W4 = (const float*)d_in[9];
    const float* b4 = (const float*)d_in[10];
    float* out = (float*)d_out;

    const int* src = ei;        // edge_index[0, :]
    const int* dst = ei + NE;   // edge_index[1, :]

    k_zero<<<(NN + 255) / 256, 256>>>();
    k_hist<<<(NE + 255) / 256, 256>>>(dst);
    k_dinv<<<(NN + 255) / 256, 256>>>();
    k_scanA<<<SCAN_B, SCAN_T>>>();
    k_scanB<<<1, 128>>>();
    k_scanC<<<SCAN_B, SCAN_T>>>();
    k_build<<<(NE + 255) / 256, 256>>>(src, dst);
    k_xw1<<<(NN * 16 + 255) / 256, 256>>>(x, W1);
    k_layer1<<<(NN + 15) / 16, 256>>>(b1, W2);
    k_layer2<<<(NN * 16 + 255) / 256, 256>>>(b2, batch);
    k_head<<<NG, 128>>>(W3, b3, W4, b4, out);
}